// round 10
// baseline (speedup 1.0000x reference)
#include <cuda_runtime.h>
#include <cuda_bf16.h>
#include <cstdint>
#include <math.h>

#define BB    8
#define CIN   256
#define CMID  128
#define PP    3600            // 60*60 positions per batch image
#define NPOS  (BB * PP)       // 28800
#define JT    57              // ceil(3600/64) j-tiles (loss)
#define IT    29              // ceil(3600/128) i-tiles

// -------- device scratch (module-scope; no runtime alloc) --------
__device__ __nv_bfloat16 g_hidbf[(size_t)2 * BB * PP * CMID];  // conv output (bf16)
__device__ __nv_bfloat16 g_featbf[(size_t)2 * BB * PP * CMID]; // normalized features (bf16)
__device__ float g_sum[256], g_sumsq[256];
__device__ float g_scale[256], g_shift[256];
__device__ float g_loss;

__device__ __forceinline__ uint32_t s2u(const void* p) {
    return (uint32_t)__cvta_generic_to_shared(p);
}
#define LDSM4(r0,r1,r2,r3,addr) \
    asm volatile("ldmatrix.sync.aligned.m8n8.x4.shared.b16 {%0,%1,%2,%3}, [%4];" \
        : "=r"(r0),"=r"(r1),"=r"(r2),"=r"(r3) : "r"(addr))
#define LDSM4T(r0,r1,r2,r3,addr) \
    asm volatile("ldmatrix.sync.aligned.m8n8.x4.trans.shared.b16 {%0,%1,%2,%3}, [%4];" \
        : "=r"(r0),"=r"(r1),"=r"(r2),"=r"(r3) : "r"(addr))
#define MMA16816(d0,d1,d2,d3,a0,a1,a2,a3,b0,b1) \
    asm volatile("mma.sync.aligned.m16n8k16.row.col.f32.bf16.bf16.f32 " \
        "{%0,%1,%2,%3}, {%4,%5,%6,%7}, {%8,%9}, {%0,%1,%2,%3};" \
        : "+f"(d0),"+f"(d1),"+f"(d2),"+f"(d3) \
        : "r"(a0),"r"(a1),"r"(a2),"r"(a3),"r"(b0),"r"(b1))

// ---------------------------------------------------------------------
__global__ void zero_kernel() {
    int t = threadIdx.x;
    if (t < 256) { g_sum[t] = 0.f; g_sumsq[t] = 0.f; }
    if (t == 0) g_loss = 0.f;
}

// ---------------------------------------------------------------------
// Kernel A (tensor): hid[p,co] = conv_w[co,:] . relu(x[:,p]) + cb[co]
// Block tile 128p x 128co, K-chunk 32. A via ldmatrix.trans (x is [ci][p]).
// BN batch sums accumulated fp32 in epilogue. grid (29, 8, 2), 256 thr.
__global__ void __launch_bounds__(256) conv_kernel(
    const float* __restrict__ x0, const float* __restrict__ x1,
    const float* __restrict__ cw, const float* __restrict__ cb)
{
    const int s = blockIdx.z, b = blockIdx.y;
    const int i0 = blockIdx.x * 128;
    const float* x = (s == 0 ? x0 : x1) + (size_t)b * CIN * PP;

    __shared__ __nv_bfloat16 Xs[32][136];   // [ci][p]  (ldmatrix.trans source)
    __shared__ __nv_bfloat16 Ws[128][40];   // [co][ci]
    __shared__ float ssum[128], ssq[128];

    const int t = threadIdx.x;
    const int wid = t >> 5, lane = t & 31;
    const int wm = wid & 3, wn = wid >> 2;
    const int mb = wm * 32, nb = wn * 64;
    const int g = lane >> 2, tg = lane & 3;
    const int lr = lane & 7, lq = lane >> 3;

    if (t < 128) { ssum[t] = 0.f; ssq[t] = 0.f; }

    float dacc[2][8][4];
#pragma unroll
    for (int mt = 0; mt < 2; mt++)
#pragma unroll
        for (int nt = 0; nt < 8; nt++)
#pragma unroll
            for (int c = 0; c < 4; c++) dacc[mt][nt][c] = 0.f;

    for (int kc = 0; kc < CIN; kc += 32) {
        __syncthreads();
        // stage Xs[ci][p]: relu + cvt, coalesced float4 reads along p
#pragma unroll
        for (int u = 0; u < 4; u++) {
            int idx = u * 256 + t;
            int ci = idx >> 5, pg = idx & 31;
            int p = i0 + pg * 4;
            float4 v = make_float4(0.f, 0.f, 0.f, 0.f);
            if (p < PP) v = *(const float4*)(x + (size_t)(kc + ci) * PP + p);
            __nv_bfloat162 h0 = __floats2bfloat162_rn(fmaxf(v.x, 0.f), fmaxf(v.y, 0.f));
            __nv_bfloat162 h1 = __floats2bfloat162_rn(fmaxf(v.z, 0.f), fmaxf(v.w, 0.f));
            uint2 pk = make_uint2(*(uint32_t*)&h0, *(uint32_t*)&h1);
            *(uint2*)&Xs[ci][pg * 4] = pk;
        }
        // stage Ws[co][ci]
#pragma unroll
        for (int u = 0; u < 4; u++) {
            int idx = u * 256 + t;
            int co = idx >> 3, f = (idx & 7) * 4;
            float4 v = *(const float4*)(cw + (size_t)co * CIN + kc + f);
            __nv_bfloat162 h0 = __floats2bfloat162_rn(v.x, v.y);
            __nv_bfloat162 h1 = __floats2bfloat162_rn(v.z, v.w);
            uint2 pk = make_uint2(*(uint32_t*)&h0, *(uint32_t*)&h1);
            *(uint2*)&Ws[co][f] = pk;
        }
        __syncthreads();

#pragma unroll
        for (int ks = 0; ks < 2; ks++) {
            uint32_t a[2][4];
#pragma unroll
            for (int mt = 0; mt < 2; mt++) {
                uint32_t addr = s2u(&Xs[ks * 16 + (lq >> 1) * 8 + lr]
                                       [mb + mt * 16 + (lq & 1) * 8]);
                LDSM4T(a[mt][0], a[mt][1], a[mt][2], a[mt][3], addr);
            }
#pragma unroll
            for (int q = 0; q < 4; q++) {
                uint32_t b0, b1, b2, b3;
                uint32_t addr = s2u(&Ws[nb + (q * 2 + (lq >> 1)) * 8 + lr]
                                       [ks * 16 + (lq & 1) * 8]);
                LDSM4(b0, b1, b2, b3, addr);
#pragma unroll
                for (int mt = 0; mt < 2; mt++) {
                    MMA16816(dacc[mt][q*2][0], dacc[mt][q*2][1],
                             dacc[mt][q*2][2], dacc[mt][q*2][3],
                             a[mt][0], a[mt][1], a[mt][2], a[mt][3], b0, b1);
                    MMA16816(dacc[mt][q*2+1][0], dacc[mt][q*2+1][1],
                             dacc[mt][q*2+1][2], dacc[mt][q*2+1][3],
                             a[mt][0], a[mt][1], a[mt][2], a[mt][3], b2, b3);
                }
            }
        }
    }

    // epilogue: bias, BN sums (fp32), store bf16
    __nv_bfloat16* hid = g_hidbf + (size_t)s * (BB * (size_t)PP * CMID)
                                 + (size_t)b * PP * CMID;
    float lsum[16], lsq[16];
#pragma unroll
    for (int i = 0; i < 16; i++) { lsum[i] = 0.f; lsq[i] = 0.f; }

#pragma unroll
    for (int mt = 0; mt < 2; mt++)
#pragma unroll
        for (int hi = 0; hi < 2; hi++) {
            int lrow = mb + mt * 16 + hi * 8 + g;
            int row = i0 + lrow;
            if (row < PP) {
#pragma unroll
                for (int nt = 0; nt < 8; nt++) {
                    int col = nb + nt * 8 + tg * 2;
                    float y0 = dacc[mt][nt][hi * 2]     + cb[col];
                    float y1 = dacc[mt][nt][hi * 2 + 1] + cb[col + 1];
                    lsum[nt*2]   += y0;  lsq[nt*2]   += y0 * y0;
                    lsum[nt*2+1] += y1;  lsq[nt*2+1] += y1 * y1;
                    __nv_bfloat162 h = __floats2bfloat162_rn(y0, y1);
                    *(uint32_t*)(hid + (size_t)row * CMID + col) = *(uint32_t*)&h;
                }
            }
        }
    // reduce over g lanes (bits 2..4 of lane), then smem atomics from g==0
#pragma unroll
    for (int i = 0; i < 16; i++) {
        lsum[i] += __shfl_xor_sync(0xffffffffu, lsum[i], 4);
        lsum[i] += __shfl_xor_sync(0xffffffffu, lsum[i], 8);
        lsum[i] += __shfl_xor_sync(0xffffffffu, lsum[i], 16);
        lsq[i]  += __shfl_xor_sync(0xffffffffu, lsq[i],  4);
        lsq[i]  += __shfl_xor_sync(0xffffffffu, lsq[i],  8);
        lsq[i]  += __shfl_xor_sync(0xffffffffu, lsq[i],  16);
    }
    if (g == 0) {
#pragma unroll
        for (int nt = 0; nt < 8; nt++) {
            int col = nb + nt * 8 + tg * 2;
            atomicAdd(&ssum[col],     lsum[nt*2]);
            atomicAdd(&ssum[col + 1], lsum[nt*2+1]);
            atomicAdd(&ssq[col],      lsq[nt*2]);
            atomicAdd(&ssq[col + 1],  lsq[nt*2+1]);
        }
    }
    __syncthreads();
    if (t < 128) {
        atomicAdd(&g_sum  [s * 128 + t], ssum[t]);
        atomicAdd(&g_sumsq[s * 128 + t], ssq[t]);
    }
}

// ---------------------------------------------------------------------
__global__ void stats_kernel(const float* __restrict__ gamma,
                             const float* __restrict__ beta)
{
    int s = blockIdx.x, c = threadIdx.x;
    if (c < 128) {
        float n = (float)NPOS;
        float mean = g_sum[s * 128 + c] / n;
        float var  = g_sumsq[s * 128 + c] / n - mean * mean;
        float rs   = rsqrtf(var + 1e-5f);
        float scl  = gamma[c] * rs;
        g_scale[s * 128 + c] = scl;
        g_shift[s * 128 + c] = beta[c] - mean * scl;
    }
}

// ---------------------------------------------------------------------
// Kernel C (tensor): feat = normalize(lin_w . relu(affine(hid)) + lb)
// Block tile 128p x 128co, K=128 staged whole. grid (29, 8, 2), 256 thr.
__global__ void __launch_bounds__(256) feat_kernel(
    const float* __restrict__ lw, const float* __restrict__ lb)
{
    extern __shared__ __align__(16) unsigned char smraw[];
    __nv_bfloat16* As = (__nv_bfloat16*)smraw;           // 128 x 136
    __nv_bfloat16* Ws = As + 128 * 136;                  // 128 x 136
    float* psum = (float*)(Ws + 128 * 136);              // 128

    const int s = blockIdx.z, b = blockIdx.y;
    const int i0 = blockIdx.x * 128;
    const int t = threadIdx.x;
    const int wid = t >> 5, lane = t & 31;
    const int wm = wid & 3, wn = wid >> 2;
    const int mb = wm * 32, nb = wn * 64;
    const int g = lane >> 2, tg = lane & 3;
    const int lr = lane & 7, lq = lane >> 3;

    const __nv_bfloat16* hid = g_hidbf + (size_t)s * (BB * (size_t)PP * CMID)
                                       + (size_t)b * PP * CMID;
    const float* sc = g_scale + s * 128;
    const float* sh = g_shift + s * 128;

    if (t < 128) psum[t] = 0.f;

    // stage As[p][k]: affine+relu in fp32, bf16 out
#pragma unroll
    for (int u = 0; u < 8; u++) {
        int idx = u * 256 + t;
        int row = idx >> 4, seg = idx & 15;
        int k0 = seg * 8;
        uint2 out[2];
        if (i0 + row < PP) {
            uint4 v = *(const uint4*)(hid + (size_t)(i0 + row) * CMID + k0);
            uint32_t w[4] = {v.x, v.y, v.z, v.w};
#pragma unroll
            for (int j = 0; j < 4; j++) {
                float2 f = __bfloat1622float2(*(__nv_bfloat162*)&w[j]);
                float y0 = fmaxf(fmaf(f.x, sc[k0 + 2*j],     sh[k0 + 2*j]),     0.f);
                float y1 = fmaxf(fmaf(f.y, sc[k0 + 2*j + 1], sh[k0 + 2*j + 1]), 0.f);
                __nv_bfloat162 h = __floats2bfloat162_rn(y0, y1);
                ((uint32_t*)out)[j] = *(uint32_t*)&h;
            }
        } else {
            out[0] = make_uint2(0u, 0u); out[1] = make_uint2(0u, 0u);
        }
        *(uint4*)&As[row * 136 + k0] = *(uint4*)out;
    }
    // stage Ws[co][k] (cvt fp32->bf16)
#pragma unroll
    for (int u = 0; u < 16; u++) {
        int idx = u * 256 + t;
        int co = idx >> 5, f = (idx & 31) * 4;
        float4 v = *(const float4*)(lw + (size_t)co * CMID + f);
        __nv_bfloat162 h0 = __floats2bfloat162_rn(v.x, v.y);
        __nv_bfloat162 h1 = __floats2bfloat162_rn(v.z, v.w);
        uint2 pk = make_uint2(*(uint32_t*)&h0, *(uint32_t*)&h1);
        *(uint2*)&Ws[co * 136 + f] = pk;
    }
    __syncthreads();

    float dacc[2][8][4];
#pragma unroll
    for (int mt = 0; mt < 2; mt++)
#pragma unroll
        for (int nt = 0; nt < 8; nt++)
#pragma unroll
            for (int c = 0; c < 4; c++) dacc[mt][nt][c] = 0.f;

#pragma unroll
    for (int ks = 0; ks < 8; ks++) {
        uint32_t a[2][4];
#pragma unroll
        for (int mt = 0; mt < 2; mt++) {
            uint32_t addr = s2u(&As[(mb + mt * 16 + (lq & 1) * 8 + lr) * 136
                                    + ks * 16 + (lq >> 1) * 8]);
            LDSM4(a[mt][0], a[mt][1], a[mt][2], a[mt][3], addr);
        }
#pragma unroll
        for (int q = 0; q < 4; q++) {
            uint32_t b0, b1, b2, b3;
            uint32_t addr = s2u(&Ws[(nb + (q * 2 + (lq >> 1)) * 8 + lr) * 136
                                    + ks * 16 + (lq & 1) * 8]);
            LDSM4(b0, b1, b2, b3, addr);
#pragma unroll
            for (int mt = 0; mt < 2; mt++) {
                MMA16816(dacc[mt][q*2][0], dacc[mt][q*2][1],
                         dacc[mt][q*2][2], dacc[mt][q*2][3],
                         a[mt][0], a[mt][1], a[mt][2], a[mt][3], b0, b1);
                MMA16816(dacc[mt][q*2+1][0], dacc[mt][q*2+1][1],
                         dacc[mt][q*2+1][2], dacc[mt][q*2+1][3],
                         a[mt][0], a[mt][1], a[mt][2], a[mt][3], b2, b3);
            }
        }
    }

    // epilogue: +bias, row sumsq -> normalize -> bf16 store
    float rsq[4] = {0.f, 0.f, 0.f, 0.f};
#pragma unroll
    for (int mt = 0; mt < 2; mt++)
#pragma unroll
        for (int hi = 0; hi < 2; hi++) {
#pragma unroll
            for (int nt = 0; nt < 8; nt++) {
                int col = nb + nt * 8 + tg * 2;
                float y0 = dacc[mt][nt][hi*2]   + lb[col];
                float y1 = dacc[mt][nt][hi*2+1] + lb[col + 1];
                dacc[mt][nt][hi*2]   = y0;
                dacc[mt][nt][hi*2+1] = y1;
                rsq[mt*2+hi] = fmaf(y0, y0, fmaf(y1, y1, rsq[mt*2+hi]));
            }
        }
#pragma unroll
    for (int r = 0; r < 4; r++) {
        rsq[r] += __shfl_xor_sync(0xffffffffu, rsq[r], 1);
        rsq[r] += __shfl_xor_sync(0xffffffffu, rsq[r], 2);
    }
    if (tg == 0) {
#pragma unroll
        for (int r = 0; r < 4; r++) {
            int lrow = mb + (r >> 1) * 16 + (r & 1) * 8 + g;
            atomicAdd(&psum[lrow], rsq[r]);
        }
    }
    __syncthreads();

    __nv_bfloat16* ft = g_featbf + (size_t)s * (BB * (size_t)PP * CMID)
                                 + (size_t)b * PP * CMID;
#pragma unroll
    for (int mt = 0; mt < 2; mt++)
#pragma unroll
        for (int hi = 0; hi < 2; hi++) {
            int lrow = mb + mt * 16 + hi * 8 + g;
            int row = i0 + lrow;
            if (row < PP) {
                float inv = 1.f / fmaxf(sqrtf(psum[lrow]), 1e-12f);
#pragma unroll
                for (int nt = 0; nt < 8; nt++) {
                    int col = nb + nt * 8 + tg * 2;
                    __nv_bfloat162 h = __floats2bfloat162_rn(
                        dacc[mt][nt][hi*2] * inv, dacc[mt][nt][hi*2+1] * inv);
                    *(uint32_t*)(ft + (size_t)row * CMID + col) = *(uint32_t*)&h;
                }
            }
        }
}

// ---------------------------------------------------------------------
// Kernel D: bf16 tensor-core logits GEMM + fused exp-sum + diag(pos) + loss.
__global__ void __launch_bounds__(256) loss_kernel()
{
    extern __shared__ __align__(16) unsigned char smraw[];
    __nv_bfloat16* obuf = (__nv_bfloat16*)smraw;         // 128 x 136
    __nv_bfloat16* tbuf = obuf + 128 * 136;              // 64 x 136
    float* rowsum = (float*)(tbuf + 64 * 136);           // 128
    float* rowpos = rowsum + 128;                        // 128
    __shared__ float cred[256];

    const int b  = blockIdx.y;
    const int i0 = blockIdx.x * 128;
    const int t  = threadIdx.x;
    const int wid = t >> 5, lane = t & 31;
    const int wm = wid & 3, wn = wid >> 2;
    const int mb = wm * 32, nb = wn * 32;
    const int g = lane >> 2, tg = lane & 3;
    const int lr = lane & 7, lq = lane >> 3;
    const float invT = 1.0f / 0.07f;

    const __nv_bfloat16* fo  = g_featbf + (size_t)b * PP * CMID;
    const __nv_bfloat16* ftg = g_featbf + (size_t)BB * PP * CMID + (size_t)b * PP * CMID;

    if (t < 128) rowsum[t] = 0.f;

#pragma unroll
    for (int u = 0; u < 8; u++) {
        int idx = u * 256 + t;
        int row = idx >> 4, seg = idx & 15;
        uint4 v = make_uint4(0u, 0u, 0u, 0u);
        int ig = i0 + row;
        if (ig < PP) v = *(const uint4*)(fo + (size_t)ig * CMID + seg * 8);
        *(uint4*)&obuf[row * 136 + seg * 8] = v;
    }
    __syncthreads();

    uint32_t a[2][8][4];
#pragma unroll
    for (int mt = 0; mt < 2; mt++)
#pragma unroll
        for (int ks = 0; ks < 8; ks++) {
            int mrow = mb + mt * 16 + (lq & 1) * 8 + lr;
            int koff = ks * 16 + (lq >> 1) * 8;
            uint32_t addr = s2u(&obuf[mrow * 136 + koff]);
            LDSM4(a[mt][ks][0], a[mt][ks][1], a[mt][ks][2], a[mt][ks][3], addr);
        }

    float dacc[2][4][4];
#pragma unroll
    for (int mt = 0; mt < 2; mt++)
#pragma unroll
        for (int nt = 0; nt < 4; nt++)
#pragma unroll
            for (int c = 0; c < 4; c++) dacc[mt][nt][c] = 0.f;
    float sacc[4] = {0.f, 0.f, 0.f, 0.f};

    for (int jt = 0; jt < JT; jt++) {
        int j0 = jt * 64;
        __syncthreads();
#pragma unroll
        for (int u = 0; u < 4; u++) {
            int idx = u * 256 + t;
            int row = idx >> 4, seg = idx & 15;
            uint4 v = make_uint4(0u, 0u, 0u, 0u);
            int jg = j0 + row;
            if (jg < PP) v = *(const uint4*)(ftg + (size_t)jg * CMID + seg * 8);
            *(uint4*)&tbuf[row * 136 + seg * 8] = v;
        }
        __syncthreads();

#pragma unroll
        for (int ks = 0; ks < 8; ks++) {
#pragma unroll
            for (int q = 0; q < 2; q++) {
                uint32_t b0, b1, b2, b3;
                int brow = nb + (q * 2 + (lq >> 1)) * 8 + lr;
                int koff = ks * 16 + (lq & 1) * 8;
                uint32_t addr = s2u(&tbuf[brow * 136 + koff]);
                LDSM4(b0, b1, b2, b3, addr);
#pragma unroll
                for (int mt = 0; mt < 2; mt++) {
                    MMA16816(dacc[mt][q*2][0], dacc[mt][q*2][1],
                             dacc[mt][q*2][2], dacc[mt][q*2][3],
                             a[mt][ks][0], a[mt][ks][1], a[mt][ks][2], a[mt][ks][3],
                             b0, b1);
                    MMA16816(dacc[mt][q*2+1][0], dacc[mt][q*2+1][1],
                             dacc[mt][q*2+1][2], dacc[mt][q*2+1][3],
                             a[mt][ks][0], a[mt][ks][1], a[mt][ks][2], a[mt][ks][3],
                             b2, b3);
                }
            }
        }

#pragma unroll
        for (int mt = 0; mt < 2; mt++)
#pragma unroll
            for (int nt = 0; nt < 4; nt++)
#pragma unroll
                for (int c = 0; c < 4; c++) {
                    float d = dacc[mt][nt][c];
                    int hi  = c >> 1;
                    int col = j0 + nb + nt * 8 + tg * 2 + (c & 1);
                    int lrow = mb + mt * 16 + hi * 8 + g;
                    if (col < PP) {
                        sacc[mt * 2 + hi] += __expf(d * invT);
                        if (col == i0 + lrow) rowpos[lrow] = d * invT;
                    }
                    dacc[mt][nt][c] = 0.f;
                }
    }

#pragma unroll
    for (int r = 0; r < 4; r++) {
        sacc[r] += __shfl_xor_sync(0xffffffffu, sacc[r], 1);
        sacc[r] += __shfl_xor_sync(0xffffffffu, sacc[r], 2);
    }
    if (tg == 0) {
#pragma unroll
        for (int r = 0; r < 4; r++) {
            int lrow = mb + (r >> 1) * 16 + (r & 1) * 8 + g;
            atomicAdd(&rowsum[lrow], sacc[r]);
        }
    }
    __syncthreads();

    float contrib = 0.f;
    if (t < 128) {
        int ig = i0 + t;
        if (ig < PP) contrib = logf(rowsum[t]) - rowpos[t];
    }
    cred[t] = contrib;
    __syncthreads();
#pragma unroll
    for (int off = 128; off > 0; off >>= 1) {
        if (t < off) cred[t] += cred[t + off];
        __syncthreads();
    }
    if (t == 0) atomicAdd(&g_loss, cred[0]);
}

// ---------------------------------------------------------------------
__global__ void finalize_kernel(float* __restrict__ out) {
    out[0] = g_loss * (1.0f / (float)NPOS);
}

// ---------------------------------------------------------------------
extern "C" void kernel_launch(void* const* d_in, const int* in_sizes, int n_in,
                              void* d_out, int out_size)
{
    const float* x0    = (const float*)d_in[0];
    const float* x1    = (const float*)d_in[1];
    const float* cw    = (const float*)d_in[2];
    const float* cb    = (const float*)d_in[3];
    const float* gamma = (const float*)d_in[4];
    const float* beta  = (const float*)d_in[5];
    const float* lw    = (const float*)d_in[6];
    const float* lb    = (const float*)d_in[7];
    float* out = (float*)d_out;

    size_t fsm = (size_t)(2 * 128 * 136) * sizeof(__nv_bfloat16)
               + 128 * sizeof(float);   // 70144 B
    cudaFuncSetAttribute((const void*)feat_kernel,
                         cudaFuncAttributeMaxDynamicSharedMemorySize, (int)fsm);
    size_t lsm = (size_t)(128 * 136 + 64 * 136) * sizeof(__nv_bfloat16)
               + 256 * sizeof(float);   // 53248 B
    cudaFuncSetAttribute((const void*)loss_kernel,
                         cudaFuncAttributeMaxDynamicSharedMemorySize, (int)lsm);

    zero_kernel<<<1, 256>>>();
    conv_kernel<<<dim3(IT, 8, 2), 256>>>(x0, x1, cw, cb);
    stats_kernel<<<2, 128>>>(gamma, beta);
    feat_kernel<<<dim3(IT, 8, 2), 256, fsm>>>(lw, lb);
    loss_kernel<<<dim3(IT, 8), 256, lsm>>>();
    finalize_kernel<<<1, 1>>>(out);
}

// round 13
// speedup vs baseline: 1.1467x; 1.1467x over previous
#include <cuda_runtime.h>
#include <cuda_bf16.h>
#include <cstdint>
#include <math.h>

#define BB    8
#define CIN   256
#define CMID  128
#define PP    3600            // 60*60 positions per batch image
#define NPOS  (BB * PP)       // 28800
#define JT    57              // ceil(3600/64) j-tiles (loss)
#define IT    29              // ceil(3600/128) i-tiles

// -------- device scratch (module-scope; no runtime alloc) --------
__device__ __nv_bfloat16 g_hidbf[(size_t)2 * BB * PP * CMID];  // conv output (bf16)
__device__ __nv_bfloat16 g_featbf[(size_t)2 * BB * PP * CMID]; // normalized features (bf16)
__device__ float g_sum[256], g_sumsq[256];
__device__ float g_scale[256], g_shift[256];
__device__ float g_loss;

__device__ __forceinline__ uint32_t s2u(const void* p) {
    return (uint32_t)__cvta_generic_to_shared(p);
}
__device__ __forceinline__ float ex2(float x) {      // EX2 (MUFU), base-2 exp
    float y;
    asm("ex2.approx.f32 %0, %1;" : "=f"(y) : "f"(x));
    return y;
}
#define LDSM4(r0,r1,r2,r3,addr) \
    asm volatile("ldmatrix.sync.aligned.m8n8.x4.shared.b16 {%0,%1,%2,%3}, [%4];" \
        : "=r"(r0),"=r"(r1),"=r"(r2),"=r"(r3) : "r"(addr))
#define LDSM4T(r0,r1,r2,r3,addr) \
    asm volatile("ldmatrix.sync.aligned.m8n8.x4.trans.shared.b16 {%0,%1,%2,%3}, [%4];" \
        : "=r"(r0),"=r"(r1),"=r"(r2),"=r"(r3) : "r"(addr))
#define MMA16816(d0,d1,d2,d3,a0,a1,a2,a3,b0,b1) \
    asm volatile("mma.sync.aligned.m16n8k16.row.col.f32.bf16.bf16.f32 " \
        "{%0,%1,%2,%3}, {%4,%5,%6,%7}, {%8,%9}, {%0,%1,%2,%3};" \
        : "+f"(d0),"+f"(d1),"+f"(d2),"+f"(d3) \
        : "r"(a0),"r"(a1),"r"(a2),"r"(a3),"r"(b0),"r"(b1))

// ---------------------------------------------------------------------
__global__ void zero_kernel() {
    int t = threadIdx.x;
    if (t < 256) { g_sum[t] = 0.f; g_sumsq[t] = 0.f; }
    if (t == 0) g_loss = 0.f;
}

// ---------------------------------------------------------------------
// Kernel A (tensor, double-buffered): hid[p,co] = cw[co,:].relu(x[:,p]) + cb
// Block tile 128p x 128co, K-chunk 32 (8 chunks), smem ping-pong, global
// prefetch to registers overlapping mma. grid (29, 8, 2), 256 thr.
__global__ void __launch_bounds__(256) conv_kernel(
    const float* __restrict__ x0, const float* __restrict__ x1,
    const float* __restrict__ cw, const float* __restrict__ cb)
{
    const int s = blockIdx.z, b = blockIdx.y;
    const int i0 = blockIdx.x * 128;
    const float* x = (s == 0 ? x0 : x1) + (size_t)b * CIN * PP;

    __shared__ __nv_bfloat16 Xs[2][32][136];
    __shared__ __nv_bfloat16 Ws[2][128][40];
    __shared__ float ssum[128], ssq[128];

    const int t = threadIdx.x;
    const int wid = t >> 5, lane = t & 31;
    const int wm = wid & 3, wn = wid >> 2;
    const int mb = wm * 32, nb = wn * 64;
    const int g = lane >> 2, tg = lane & 3;
    const int lr = lane & 7, lq = lane >> 3;

    if (t < 128) { ssum[t] = 0.f; ssq[t] = 0.f; }

    // per-thread staging coordinates (u = 0..3)
    const int xci = t >> 5, xpg = t & 31;          // +8*u on ci
    const int wco = t >> 3, wf  = (t & 7) * 4;     // +32*u on co

    float4 xv[4], wv[4];
    // ---- prefetch chunk 0 ----
#pragma unroll
    for (int u = 0; u < 4; u++) {
        int p = i0 + xpg * 4;
        xv[u] = make_float4(0.f, 0.f, 0.f, 0.f);
        if (p < PP) xv[u] = *(const float4*)(x + (size_t)(xci + u * 8) * PP + p);
        wv[u] = *(const float4*)(cw + (size_t)(wco + u * 32) * CIN + wf);
    }
    // ---- store chunk 0 to buf 0 ----
#pragma unroll
    for (int u = 0; u < 4; u++) {
        __nv_bfloat162 h0 = __floats2bfloat162_rn(fmaxf(xv[u].x, 0.f), fmaxf(xv[u].y, 0.f));
        __nv_bfloat162 h1 = __floats2bfloat162_rn(fmaxf(xv[u].z, 0.f), fmaxf(xv[u].w, 0.f));
        *(uint2*)&Xs[0][xci + u * 8][xpg * 4] =
            make_uint2(*(uint32_t*)&h0, *(uint32_t*)&h1);
        __nv_bfloat162 g0 = __floats2bfloat162_rn(wv[u].x, wv[u].y);
        __nv_bfloat162 g1 = __floats2bfloat162_rn(wv[u].z, wv[u].w);
        *(uint2*)&Ws[0][wco + u * 32][wf] =
            make_uint2(*(uint32_t*)&g0, *(uint32_t*)&g1);
    }
    __syncthreads();

    float dacc[2][8][4];
#pragma unroll
    for (int mt = 0; mt < 2; mt++)
#pragma unroll
        for (int nt = 0; nt < 8; nt++)
#pragma unroll
            for (int c = 0; c < 4; c++) dacc[mt][nt][c] = 0.f;

    for (int chunk = 0; chunk < 8; chunk++) {
        const int cur = chunk & 1;
        // prefetch chunk+1 (overlaps with mma below)
        if (chunk < 7) {
            int kc = (chunk + 1) * 32;
#pragma unroll
            for (int u = 0; u < 4; u++) {
                int p = i0 + xpg * 4;
                xv[u] = make_float4(0.f, 0.f, 0.f, 0.f);
                if (p < PP)
                    xv[u] = *(const float4*)(x + (size_t)(kc + xci + u * 8) * PP + p);
                wv[u] = *(const float4*)(cw + (size_t)(wco + u * 32) * CIN + kc + wf);
            }
        }
        // mma on buf cur
#pragma unroll
        for (int ks = 0; ks < 2; ks++) {
            uint32_t a[2][4];
#pragma unroll
            for (int mt = 0; mt < 2; mt++) {
                uint32_t addr = s2u(&Xs[cur][ks * 16 + (lq >> 1) * 8 + lr]
                                          [mb + mt * 16 + (lq & 1) * 8]);
                LDSM4T(a[mt][0], a[mt][1], a[mt][2], a[mt][3], addr);
            }
#pragma unroll
            for (int q = 0; q < 4; q++) {
                uint32_t b0, b1, b2, b3;
                uint32_t addr = s2u(&Ws[cur][nb + (q * 2 + (lq >> 1)) * 8 + lr]
                                          [ks * 16 + (lq & 1) * 8]);
                LDSM4(b0, b1, b2, b3, addr);
#pragma unroll
                for (int mt = 0; mt < 2; mt++) {
                    MMA16816(dacc[mt][q*2][0], dacc[mt][q*2][1],
                             dacc[mt][q*2][2], dacc[mt][q*2][3],
                             a[mt][0], a[mt][1], a[mt][2], a[mt][3], b0, b1);
                    MMA16816(dacc[mt][q*2+1][0], dacc[mt][q*2+1][1],
                             dacc[mt][q*2+1][2], dacc[mt][q*2+1][3],
                             a[mt][0], a[mt][1], a[mt][2], a[mt][3], b2, b3);
                }
            }
        }
        // store chunk+1 into the other buffer
        if (chunk < 7) {
            const int nxt = cur ^ 1;
#pragma unroll
            for (int u = 0; u < 4; u++) {
                __nv_bfloat162 h0 = __floats2bfloat162_rn(fmaxf(xv[u].x, 0.f), fmaxf(xv[u].y, 0.f));
                __nv_bfloat162 h1 = __floats2bfloat162_rn(fmaxf(xv[u].z, 0.f), fmaxf(xv[u].w, 0.f));
                *(uint2*)&Xs[nxt][xci + u * 8][xpg * 4] =
                    make_uint2(*(uint32_t*)&h0, *(uint32_t*)&h1);
                __nv_bfloat162 g0 = __floats2bfloat162_rn(wv[u].x, wv[u].y);
                __nv_bfloat162 g1 = __floats2bfloat162_rn(wv[u].z, wv[u].w);
                *(uint2*)&Ws[nxt][wco + u * 32][wf] =
                    make_uint2(*(uint32_t*)&g0, *(uint32_t*)&g1);
            }
        }
        __syncthreads();
    }

    // epilogue: bias, BN sums (fp32), store bf16
    __nv_bfloat16* hid = g_hidbf + (size_t)s * (BB * (size_t)PP * CMID)
                                 + (size_t)b * PP * CMID;
    float lsum[16], lsq[16];
#pragma unroll
    for (int i = 0; i < 16; i++) { lsum[i] = 0.f; lsq[i] = 0.f; }

#pragma unroll
    for (int mt = 0; mt < 2; mt++)
#pragma unroll
        for (int hi = 0; hi < 2; hi++) {
            int lrow = mb + mt * 16 + hi * 8 + g;
            int row = i0 + lrow;
            if (row < PP) {
#pragma unroll
                for (int nt = 0; nt < 8; nt++) {
                    int col = nb + nt * 8 + tg * 2;
                    float y0 = dacc[mt][nt][hi * 2]     + cb[col];
                    float y1 = dacc[mt][nt][hi * 2 + 1] + cb[col + 1];
                    lsum[nt*2]   += y0;  lsq[nt*2]   += y0 * y0;
                    lsum[nt*2+1] += y1;  lsq[nt*2+1] += y1 * y1;
                    __nv_bfloat162 h = __floats2bfloat162_rn(y0, y1);
                    *(uint32_t*)(hid + (size_t)row * CMID + col) = *(uint32_t*)&h;
                }
            }
        }
#pragma unroll
    for (int i = 0; i < 16; i++) {
        lsum[i] += __shfl_xor_sync(0xffffffffu, lsum[i], 4);
        lsum[i] += __shfl_xor_sync(0xffffffffu, lsum[i], 8);
        lsum[i] += __shfl_xor_sync(0xffffffffu, lsum[i], 16);
        lsq[i]  += __shfl_xor_sync(0xffffffffu, lsq[i],  4);
        lsq[i]  += __shfl_xor_sync(0xffffffffu, lsq[i],  8);
        lsq[i]  += __shfl_xor_sync(0xffffffffu, lsq[i],  16);
    }
    if (g == 0) {
#pragma unroll
        for (int nt = 0; nt < 8; nt++) {
            int col = nb + nt * 8 + tg * 2;
            atomicAdd(&ssum[col],     lsum[nt*2]);
            atomicAdd(&ssum[col + 1], lsum[nt*2+1]);
            atomicAdd(&ssq[col],      lsq[nt*2]);
            atomicAdd(&ssq[col + 1],  lsq[nt*2+1]);
        }
    }
    __syncthreads();
    if (t < 128) {
        atomicAdd(&g_sum  [s * 128 + t], ssum[t]);
        atomicAdd(&g_sumsq[s * 128 + t], ssq[t]);
    }
}

// ---------------------------------------------------------------------
__global__ void stats_kernel(const float* __restrict__ gamma,
                             const float* __restrict__ beta)
{
    int s = blockIdx.x, c = threadIdx.x;
    if (c < 128) {
        float n = (float)NPOS;
        float mean = g_sum[s * 128 + c] / n;
        float var  = g_sumsq[s * 128 + c] / n - mean * mean;
        float rs   = rsqrtf(var + 1e-5f);
        float scl  = gamma[c] * rs;
        g_scale[s * 128 + c] = scl;
        g_shift[s * 128 + c] = beta[c] - mean * scl;
    }
}

// ---------------------------------------------------------------------
// Kernel C (tensor): feat = normalize(lin_w . relu(affine(hid)) + lb)
__global__ void __launch_bounds__(256) feat_kernel(
    const float* __restrict__ lw, const float* __restrict__ lb)
{
    extern __shared__ __align__(16) unsigned char smraw[];
    __nv_bfloat16* As = (__nv_bfloat16*)smraw;           // 128 x 136
    __nv_bfloat16* Ws = As + 128 * 136;                  // 128 x 136
    float* psum = (float*)(Ws + 128 * 136);              // 128

    const int s = blockIdx.z, b = blockIdx.y;
    const int i0 = blockIdx.x * 128;
    const int t = threadIdx.x;
    const int wid = t >> 5, lane = t & 31;
    const int wm = wid & 3, wn = wid >> 2;
    const int mb = wm * 32, nb = wn * 64;
    const int g = lane >> 2, tg = lane & 3;
    const int lr = lane & 7, lq = lane >> 3;

    const __nv_bfloat16* hid = g_hidbf + (size_t)s * (BB * (size_t)PP * CMID)
                                       + (size_t)b * PP * CMID;
    const float* sc = g_scale + s * 128;
    const float* sh = g_shift + s * 128;

    if (t < 128) psum[t] = 0.f;

#pragma unroll
    for (int u = 0; u < 8; u++) {
        int idx = u * 256 + t;
        int row = idx >> 4, seg = idx & 15;
        int k0 = seg * 8;
        uint2 out[2];
        if (i0 + row < PP) {
            uint4 v = *(const uint4*)(hid + (size_t)(i0 + row) * CMID + k0);
            uint32_t w[4] = {v.x, v.y, v.z, v.w};
#pragma unroll
            for (int j = 0; j < 4; j++) {
                float2 f = __bfloat1622float2(*(__nv_bfloat162*)&w[j]);
                float y0 = fmaxf(fmaf(f.x, sc[k0 + 2*j],     sh[k0 + 2*j]),     0.f);
                float y1 = fmaxf(fmaf(f.y, sc[k0 + 2*j + 1], sh[k0 + 2*j + 1]), 0.f);
                __nv_bfloat162 h = __floats2bfloat162_rn(y0, y1);
                ((uint32_t*)out)[j] = *(uint32_t*)&h;
            }
        } else {
            out[0] = make_uint2(0u, 0u); out[1] = make_uint2(0u, 0u);
        }
        *(uint4*)&As[row * 136 + k0] = *(uint4*)out;
    }
#pragma unroll
    for (int u = 0; u < 16; u++) {
        int idx = u * 256 + t;
        int co = idx >> 5, f = (idx & 31) * 4;
        float4 v = *(const float4*)(lw + (size_t)co * CMID + f);
        __nv_bfloat162 h0 = __floats2bfloat162_rn(v.x, v.y);
        __nv_bfloat162 h1 = __floats2bfloat162_rn(v.z, v.w);
        uint2 pk = make_uint2(*(uint32_t*)&h0, *(uint32_t*)&h1);
        *(uint2*)&Ws[co * 136 + f] = pk;
    }
    __syncthreads();

    float dacc[2][8][4];
#pragma unroll
    for (int mt = 0; mt < 2; mt++)
#pragma unroll
        for (int nt = 0; nt < 8; nt++)
#pragma unroll
            for (int c = 0; c < 4; c++) dacc[mt][nt][c] = 0.f;

#pragma unroll
    for (int ks = 0; ks < 8; ks++) {
        uint32_t a[2][4];
#pragma unroll
        for (int mt = 0; mt < 2; mt++) {
            uint32_t addr = s2u(&As[(mb + mt * 16 + (lq & 1) * 8 + lr) * 136
                                    + ks * 16 + (lq >> 1) * 8]);
            LDSM4(a[mt][0], a[mt][1], a[mt][2], a[mt][3], addr);
        }
#pragma unroll
        for (int q = 0; q < 4; q++) {
            uint32_t b0, b1, b2, b3;
            uint32_t addr = s2u(&Ws[(nb + (q * 2 + (lq >> 1)) * 8 + lr) * 136
                                    + ks * 16 + (lq & 1) * 8]);
            LDSM4(b0, b1, b2, b3, addr);
#pragma unroll
            for (int mt = 0; mt < 2; mt++) {
                MMA16816(dacc[mt][q*2][0], dacc[mt][q*2][1],
                         dacc[mt][q*2][2], dacc[mt][q*2][3],
                         a[mt][0], a[mt][1], a[mt][2], a[mt][3], b0, b1);
                MMA16816(dacc[mt][q*2+1][0], dacc[mt][q*2+1][1],
                         dacc[mt][q*2+1][2], dacc[mt][q*2+1][3],
                         a[mt][0], a[mt][1], a[mt][2], a[mt][3], b2, b3);
            }
        }
    }

    float rsq[4] = {0.f, 0.f, 0.f, 0.f};
#pragma unroll
    for (int mt = 0; mt < 2; mt++)
#pragma unroll
        for (int hi = 0; hi < 2; hi++) {
#pragma unroll
            for (int nt = 0; nt < 8; nt++) {
                int col = nb + nt * 8 + tg * 2;
                float y0 = dacc[mt][nt][hi*2]   + lb[col];
                float y1 = dacc[mt][nt][hi*2+1] + lb[col + 1];
                dacc[mt][nt][hi*2]   = y0;
                dacc[mt][nt][hi*2+1] = y1;
                rsq[mt*2+hi] = fmaf(y0, y0, fmaf(y1, y1, rsq[mt*2+hi]));
            }
        }
#pragma unroll
    for (int r = 0; r < 4; r++) {
        rsq[r] += __shfl_xor_sync(0xffffffffu, rsq[r], 1);
        rsq[r] += __shfl_xor_sync(0xffffffffu, rsq[r], 2);
    }
    if (tg == 0) {
#pragma unroll
        for (int r = 0; r < 4; r++) {
            int lrow = mb + (r >> 1) * 16 + (r & 1) * 8 + g;
            atomicAdd(&psum[lrow], rsq[r]);
        }
    }
    __syncthreads();

    __nv_bfloat16* ft = g_featbf + (size_t)s * (BB * (size_t)PP * CMID)
                                 + (size_t)b * PP * CMID;
#pragma unroll
    for (int mt = 0; mt < 2; mt++)
#pragma unroll
        for (int hi = 0; hi < 2; hi++) {
            int lrow = mb + mt * 16 + hi * 8 + g;
            int row = i0 + lrow;
            if (row < PP) {
                float inv = 1.f / fmaxf(sqrtf(psum[lrow]), 1e-12f);
#pragma unroll
                for (int nt = 0; nt < 8; nt++) {
                    int col = nb + nt * 8 + tg * 2;
                    __nv_bfloat162 h = __floats2bfloat162_rn(
                        dacc[mt][nt][hi*2] * inv, dacc[mt][nt][hi*2+1] * inv);
                    *(uint32_t*)(ft + (size_t)row * CMID + col) = *(uint32_t*)&h;
                }
            }
        }
}

// ---------------------------------------------------------------------
// Kernel D: bf16 mma.sync logits GEMM + fused exp-sum + diag + loss.
// occupancy 2 (one full wave of 232 CTAs); fast path for non-diag full
// tiles (no predication); exp via MUFU ex2.approx.
__global__ void __launch_bounds__(256, 2) loss_kernel()
{
    extern __shared__ __align__(16) unsigned char smraw[];
    __nv_bfloat16* obuf = (__nv_bfloat16*)smraw;         // 128 x 136
    __nv_bfloat16* tbuf = obuf + 128 * 136;              // 64 x 136
    float* rowsum = (float*)(tbuf + 64 * 136);           // 128
    float* rowpos = rowsum + 128;                        // 128
    __shared__ float cred[256];

    const int b  = blockIdx.y;
    const int i0 = blockIdx.x * 128;
    const int t  = threadIdx.x;
    const int wid = t >> 5, lane = t & 31;
    const int wm = wid & 3, wn = wid >> 2;
    const int mb = wm * 32, nb = wn * 32;
    const int g = lane >> 2, tg = lane & 3;
    const int lr = lane & 7, lq = lane >> 3;
    const float invT = 1.0f / 0.07f;
    const float C2 = invT * 1.44269504088896f;   // invT * log2(e)

    const __nv_bfloat16* fo  = g_featbf + (size_t)b * PP * CMID;
    const __nv_bfloat16* ftg = g_featbf + (size_t)BB * PP * CMID + (size_t)b * PP * CMID;

    if (t < 128) rowsum[t] = 0.f;

#pragma unroll
    for (int u = 0; u < 8; u++) {
        int idx = u * 256 + t;
        int row = idx >> 4, seg = idx & 15;
        uint4 v = make_uint4(0u, 0u, 0u, 0u);
        int ig = i0 + row;
        if (ig < PP) v = *(const uint4*)(fo + (size_t)ig * CMID + seg * 8);
        *(uint4*)&obuf[row * 136 + seg * 8] = v;
    }
    __syncthreads();

    uint32_t a[2][8][4];
#pragma unroll
    for (int mt = 0; mt < 2; mt++)
#pragma unroll
        for (int ks = 0; ks < 8; ks++) {
            int mrow = mb + mt * 16 + (lq & 1) * 8 + lr;
            int koff = ks * 16 + (lq >> 1) * 8;
            uint32_t addr = s2u(&obuf[mrow * 136 + koff]);
            LDSM4(a[mt][ks][0], a[mt][ks][1], a[mt][ks][2], a[mt][ks][3], addr);
        }

    float dacc[2][4][4];
#pragma unroll
    for (int mt = 0; mt < 2; mt++)
#pragma unroll
        for (int nt = 0; nt < 4; nt++)
#pragma unroll
            for (int c = 0; c < 4; c++) dacc[mt][nt][c] = 0.f;
    float sacc[4] = {0.f, 0.f, 0.f, 0.f};

    for (int jt = 0; jt < JT; jt++) {
        int j0 = jt * 64;
        __syncthreads();
#pragma unroll
        for (int u = 0; u < 4; u++) {
            int idx = u * 256 + t;
            int row = idx >> 4, seg = idx & 15;
            uint4 v = make_uint4(0u, 0u, 0u, 0u);
            int jg = j0 + row;
            if (jg < PP) v = *(const uint4*)(ftg + (size_t)jg * CMID + seg * 8);
            *(uint4*)&tbuf[row * 136 + seg * 8] = v;
        }
        __syncthreads();

#pragma unroll
        for (int ks = 0; ks < 8; ks++) {
#pragma unroll
            for (int q = 0; q < 2; q++) {
                uint32_t b0, b1, b2, b3;
                int brow = nb + (q * 2 + (lq >> 1)) * 8 + lr;
                int koff = ks * 16 + (lq & 1) * 8;
                uint32_t addr = s2u(&tbuf[brow * 136 + koff]);
                LDSM4(b0, b1, b2, b3, addr);
#pragma unroll
                for (int mt = 0; mt < 2; mt++) {
                    MMA16816(dacc[mt][q*2][0], dacc[mt][q*2][1],
                             dacc[mt][q*2][2], dacc[mt][q*2][3],
                             a[mt][ks][0], a[mt][ks][1], a[mt][ks][2], a[mt][ks][3],
                             b0, b1);
                    MMA16816(dacc[mt][q*2+1][0], dacc[mt][q*2+1][1],
                             dacc[mt][q*2+1][2], dacc[mt][q*2+1][3],
                             a[mt][ks][0], a[mt][ks][1], a[mt][ks][2], a[mt][ks][3],
                             b2, b3);
                }
            }
        }

        // epilogue
        int dj = jt - (blockIdx.x << 1);
        if (jt < 56 && (unsigned)dj > 1u) {
            // fast path: full tile, no diagonal, no bounds checks
#pragma unroll
            for (int mt = 0; mt < 2; mt++)
#pragma unroll
                for (int nt = 0; nt < 4; nt++)
#pragma unroll
                    for (int c = 0; c < 4; c++) {
                        sacc[mt * 2 + (c >> 1)] += ex2(dacc[mt][nt][c] * C2);
                        dacc[mt][nt][c] = 0.f;
                    }
        } else {
            // slow path: partial tile and/or diagonal tile
#pragma unroll
            for (int mt = 0; mt < 2; mt++)
#pragma unroll
                for (int nt = 0; nt < 4; nt++)
#pragma unroll
                    for (int c = 0; c < 4; c++) {
                        float d = dacc[mt][nt][c];
                        int hi  = c >> 1;
                        int col = j0 + nb + nt * 8 + tg * 2 + (c & 1);
                        int lrow = mb + mt * 16 + hi * 8 + g;
                        if (col < PP) {
                            sacc[mt * 2 + hi] += ex2(d * C2);
                            if (col == i0 + lrow) rowpos[lrow] = d * invT;
                        }
                        dacc[mt][nt][c] = 0.f;
                    }
        }
    }

#pragma unroll
    for (int r = 0; r < 4; r++) {
        sacc[r] += __shfl_xor_sync(0xffffffffu, sacc[r], 1);
        sacc[r] += __shfl_xor_sync(0xffffffffu, sacc[r], 2);
    }
    if (tg == 0) {
#pragma unroll
        for (int r = 0; r < 4; r++) {
            int lrow = mb + (r >> 1) * 16 + (r & 1) * 8 + g;
            atomicAdd(&rowsum[lrow], sacc[r]);
        }
    }
    __syncthreads();

    float contrib = 0.f;
    if (t < 128) {
        int ig = i0 + t;
        if (ig < PP) contrib = logf(rowsum[t]) - rowpos[t];
    }
    cred[t] = contrib;
    __syncthreads();
#pragma unroll
    for (int off = 128; off > 0; off >>= 1) {
        if (t < off) cred[t] += cred[t + off];
        __syncthreads();
    }
    if (t == 0) atomicAdd(&g_loss, cred[0]);
}

// ---------------------------------------------------------------------
__global__ void finalize_kernel(float* __restrict__ out) {
    out[0] = g_loss * (1.0f / (float)NPOS);
}

// ---------------------------------------------------------------------
extern "C" void kernel_launch(void* const* d_in, const int* in_sizes, int n_in,
                              void* d_out, int out_size)
{
    const float* x0    = (const float*)d_in[0];
    const float* x1    = (const float*)d_in[1];
    const float* cw    = (const float*)d_in[2];
    const float* cb    = (const float*)d_in[3];
    const float* gamma = (const float*)d_in[4];
    const float* beta  = (const float*)d_in[5];
    const float* lw    = (const float*)d_in[6];
    const float* lb    = (const float*)d_in[7];
    float* out = (float*)d_out;

    size_t fsm = (size_t)(2 * 128 * 136) * sizeof(__nv_bfloat16)
               + 128 * sizeof(float);   // 70144 B
    cudaFuncSetAttribute((const void*)feat_kernel,
                         cudaFuncAttributeMaxDynamicSharedMemorySize, (int)fsm);
    size_t lsm = (size_t)(128 * 136 + 64 * 136) * sizeof(__nv_bfloat16)
               + 256 * sizeof(float);   // 53248 B
    cudaFuncSetAttribute((const void*)loss_kernel,
                         cudaFuncAttributeMaxDynamicSharedMemorySize, (int)lsm);

    zero_kernel<<<1, 256>>>();
    conv_kernel<<<dim3(IT, 8, 2), 256>>>(x0, x1, cw, cb);
    stats_kernel<<<2, 128>>>(gamma, beta);
    feat_kernel<<<dim3(IT, 8, 2), 256, fsm>>>(lw, lb);
    loss_kernel<<<dim3(IT, 8), 256, lsm>>>();
    finalize_kernel<<<1, 1>>>(out);
}